// round 7
// baseline (speedup 1.0000x reference)
#include <cuda_runtime.h>

// LSTM B=2048, T=512, LATENT=18, HID=32 (gates i,f,g,o).
// Kernel 1 (serial recurrence): 128 blocks x 256 threads (2 warps/SMSP).
//   Warp = 2 batch elems; lane = hidden index; weights register-resident as
//   f32x2 pairs. R7: software-pipelined — each step computes the NEXT step's
//   input-gate contribution (independent of h) between the recurrent loop and
//   the pointwise, so ptxas fills the MUFU/dependency tail with FFMA2s.
//   2-unrolled with x0/x1 register-array swap; accumulator aliases current x.
// Kernel 2 (proj): 128-row tiles, coalesced LDG -> XOR-swizzled smem ->
//   2 threads/row compute 9 outputs each -> staged coalesced store.

#define NB 2048
#define NT 512
#define NL 18
#define NH 32
#define NP 9     // latent pairs
#define KP 16    // hidden pairs

typedef unsigned long long u64;

__device__ float g_hscr[(size_t)NB * NT * NH];   // scratch h[B][T][32]

__device__ __forceinline__ u64 pk(float x, float y) {
    u64 r; asm("mov.b64 %0,{%1,%2};" : "=l"(r) : "f"(x), "f"(y)); return r;
}
__device__ __forceinline__ void upk(u64 v, float& x, float& y) {
    asm("mov.b64 {%0,%1},%2;" : "=f"(x), "=f"(y) : "l"(v));
}
__device__ __forceinline__ u64 ffma2(u64 a, u64 b, u64 c) {
    u64 d; asm("fma.rn.f32x2 %0,%1,%2,%3;" : "=l"(d) : "l"(a), "l"(b), "l"(c));
    return d;
}
__device__ __forceinline__ float ex2(float x) {
    float r; asm("ex2.approx.f32 %0,%1;" : "=f"(r) : "f"(x)); return r;
}
__device__ __forceinline__ float rcp(float x) {
    float r; asm("rcp.approx.f32 %0,%1;" : "=f"(r) : "f"(x)); return r;
}
__device__ __forceinline__ float sigmoid_fast(float x) {
    return rcp(1.0f + ex2(-1.4426950408889634f * x));
}
__device__ __forceinline__ float tanh_fast(float x) {
    return 1.0f - 2.0f * rcp(ex2(2.8853900817779268f * x) + 1.0f);
}

__global__ __launch_bounds__(256, 1)
void lstm_rec_kernel(const float* __restrict__ z,
                     const float* __restrict__ Wih,
                     const float* __restrict__ Whh,
                     const float* __restrict__ bih,
                     const float* __restrict__ bhh,
                     float* __restrict__ out)
{
    __shared__ u64 sZ[8][2][NP];   // [warp][elem][k] = (z_2k, z_2k+1)
    __shared__ u64 sH[8][2][KP];   // [warp][elem][k] = (h_2k, h_2k+1)

    const int tid  = threadIdx.x;
    const int warp = tid >> 5;
    const int lane = tid & 31;
    const int be   = blockIdx.x * 16 + warp * 2;

    // register-resident weights (gate rows lane, 32+lane, 64+lane, 96+lane)
    u64 vI[NP], vF[NP], vG[NP], vO[NP];      // W_ih pairs
    u64 wI[KP], wF[KP], wG[KP], wO[KP];      // W_hh pairs
    {
        const u64* ri = (const u64*)(Wih + (size_t)lane * NL);
        const u64* rf = (const u64*)(Wih + (size_t)(32 + lane) * NL);
        const u64* rg = (const u64*)(Wih + (size_t)(64 + lane) * NL);
        const u64* ro = (const u64*)(Wih + (size_t)(96 + lane) * NL);
        #pragma unroll
        for (int k = 0; k < NP; k++) {
            vI[k] = ri[k]; vF[k] = rf[k]; vG[k] = rg[k]; vO[k] = ro[k];
        }
    }
    {
        const u64* ri = (const u64*)(Whh + (size_t)lane * NH);
        const u64* rf = (const u64*)(Whh + (size_t)(32 + lane) * NH);
        const u64* rg = (const u64*)(Whh + (size_t)(64 + lane) * NH);
        const u64* ro = (const u64*)(Whh + (size_t)(96 + lane) * NH);
        #pragma unroll
        for (int k = 0; k < KP; k++) {
            wI[k] = ri[k]; wF[k] = rf[k]; wG[k] = rg[k]; wO[k] = ro[k];
        }
    }

    const float bIf = bih[lane]      + bhh[lane];
    const float bFf = bih[32 + lane] + bhh[32 + lane];
    const float bGf = bih[64 + lane] + bhh[64 + lane];
    const float bOf = bih[96 + lane] + bhh[96 + lane];

    if (lane < KP) {
        sH[warp][0][lane] = 0ull;
        sH[warp][1][lane] = 0ull;
    }

    // z pointers; elem-1 addressed via compile-time byte offset from elem-0
    const float* zb0 = z + ((size_t)be * NT) * NL + 2 * lane;
    float* hs0 = g_hscr + ((size_t)be * NT) * NH + lane;
    const size_t ZOFS = (size_t)NT * NL;   // elem stride in floats
    const size_t HOFS = (size_t)NT * NH;

    u64 zp0 = 0, zp1 = 0;
    if (lane < NP) {
        zp0 = *(const u64*)zb0;
        zp1 = *(const u64*)(zb0 + ZOFS);
    }
    float c0 = 0.f, c1 = 0.f, h0 = 0.f, h1 = 0.f;

    // x buffers: [0..3] = elem0 gates i,f,g,o ; [4..7] = elem1
    u64 x0[8], x1[8];

    // ---- prelude: stage z_0, build x0, prefetch z_1 ----
    if (lane < NP) {
        sZ[warp][0][lane] = zp0;
        sZ[warp][1][lane] = zp1;
    }
    __syncwarp();
    {
        x0[0] = pk(bIf, 0.f); x0[1] = pk(bFf, 0.f);
        x0[2] = pk(bGf, 0.f); x0[3] = pk(bOf, 0.f);
        x0[4] = x0[0]; x0[5] = x0[1]; x0[6] = x0[2]; x0[7] = x0[3];
        #pragma unroll
        for (int k = 0; k < NP; k++) {
            u64 za = sZ[warp][0][k];
            u64 zb = sZ[warp][1][k];
            x0[0] = ffma2(za, vI[k], x0[0]);  x0[4] = ffma2(zb, vI[k], x0[4]);
            x0[1] = ffma2(za, vF[k], x0[1]);  x0[5] = ffma2(zb, vF[k], x0[5]);
            x0[2] = ffma2(za, vG[k], x0[2]);  x0[6] = ffma2(zb, vG[k], x0[6]);
            x0[3] = ffma2(za, vO[k], x0[3]);  x0[7] = ffma2(zb, vO[k], x0[7]);
        }
    }
    if (lane < NP) {   // z_1
        zp0 = *(const u64*)(zb0 + (size_t)1 * NL);
        zp1 = *(const u64*)(zb0 + ZOFS + (size_t)1 * NL);
    }
    __syncwarp();   // NP reads of sZ done before STEP(0)'s stage overwrites

#define STEP(T, XC, XN)                                                        \
    do {                                                                       \
        /* recurrent accumulation directly into XC (becomes gate pre-act) */   \
        _Pragma("unroll")                                                      \
        for (int k = 0; k < KP; k++) {                                         \
            u64 p0 = sH[warp][0][k];                                           \
            u64 p1 = sH[warp][1][k];                                           \
            XC[0] = ffma2(p0, wI[k], XC[0]);  XC[4] = ffma2(p1, wI[k], XC[4]); \
            XC[1] = ffma2(p0, wF[k], XC[1]);  XC[5] = ffma2(p1, wF[k], XC[5]); \
            XC[2] = ffma2(p0, wG[k], XC[2]);  XC[6] = ffma2(p1, wG[k], XC[6]); \
            XC[3] = ffma2(p0, wO[k], XC[3]);  XC[7] = ffma2(p1, wO[k], XC[7]); \
        }                                                                      \
        if (lane < NP) {   /* stage z_{T+1} */                                 \
            sZ[warp][0][lane] = zp0;                                           \
            sZ[warp][1][lane] = zp1;                                           \
        }                                                                      \
        __syncwarp();  /* sZ visible; KP sH-reads done before sH overwrite */  \
        if (lane < NP && (T) + 2 < NT) {   /* prefetch z_{T+2} */              \
            zp0 = *(const u64*)(zb0 + (size_t)((T) + 2) * NL);                 \
            zp1 = *(const u64*)(zb0 + ZOFS + (size_t)((T) + 2) * NL);          \
        }                                                                      \
        /* independent filler: build x for step T+1 (interleaves with MUFU) */ \
        XN[0] = pk(bIf, 0.f); XN[1] = pk(bFf, 0.f);                            \
        XN[2] = pk(bGf, 0.f); XN[3] = pk(bOf, 0.f);                            \
        XN[4] = XN[0]; XN[5] = XN[1]; XN[6] = XN[2]; XN[7] = XN[3];            \
        _Pragma("unroll")                                                      \
        for (int k = 0; k < NP; k++) {                                         \
            u64 za = sZ[warp][0][k];                                           \
            u64 zb = sZ[warp][1][k];                                           \
            XN[0] = ffma2(za, vI[k], XN[0]);  XN[4] = ffma2(zb, vI[k], XN[4]); \
            XN[1] = ffma2(za, vF[k], XN[1]);  XN[5] = ffma2(zb, vF[k], XN[5]); \
            XN[2] = ffma2(za, vG[k], XN[2]);  XN[6] = ffma2(zb, vG[k], XN[6]); \
            XN[3] = ffma2(za, vO[k], XN[3]);  XN[7] = ffma2(zb, vO[k], XN[7]); \
        }                                                                      \
        /* pointwise */                                                        \
        {                                                                      \
            float xa, ya, vi, vf, vg, vo, ii, ff, gg, oo;                      \
            upk(XC[0], xa, ya); vi = xa + ya;                                  \
            upk(XC[1], xa, ya); vf = xa + ya;                                  \
            upk(XC[2], xa, ya); vg = xa + ya;                                  \
            upk(XC[3], xa, ya); vo = xa + ya;                                  \
            ii = sigmoid_fast(vi); ff = sigmoid_fast(vf);                      \
            gg = tanh_fast(vg);    oo = sigmoid_fast(vo);                      \
            c0 = ff * c0 + ii * gg;                                            \
            h0 = oo * tanh_fast(c0);                                           \
            upk(XC[4], xa, ya); vi = xa + ya;                                  \
            upk(XC[5], xa, ya); vf = xa + ya;                                  \
            upk(XC[6], xa, ya); vg = xa + ya;                                  \
            upk(XC[7], xa, ya); vo = xa + ya;                                  \
            ii = sigmoid_fast(vi); ff = sigmoid_fast(vf);                      \
            gg = tanh_fast(vg);    oo = sigmoid_fast(vo);                      \
            c1 = ff * c1 + ii * gg;                                            \
            h1 = oo * tanh_fast(c1);                                           \
        }                                                                      \
        {                                                                      \
            float hn0 = __shfl_down_sync(0xffffffffu, h0, 1);                  \
            float hn1 = __shfl_down_sync(0xffffffffu, h1, 1);                  \
            if (!(lane & 1)) {                                                 \
                sH[warp][0][lane >> 1] = pk(h0, hn0);                          \
                sH[warp][1][lane >> 1] = pk(h1, hn1);                          \
            }                                                                  \
        }                                                                      \
        hs0[(size_t)(T) * NH]        = h0;                                     \
        hs0[HOFS + (size_t)(T) * NH] = h1;                                     \
        __syncwarp();  /* sH visible before next KP; NP reads done */          \
    } while (0)

    for (int t = 0; t < NT; t += 2) {
        STEP(t,     x0, x1);
        STEP(t + 1, x1, x0);
    }
#undef STEP

    // out layout: [z_pred (B*T*18) | h_n (B*32) | c_n (B*32)]
    float* hOut = out + (size_t)NB * NT * NL;
    float* cOut = hOut + (size_t)NB * NH;
    hOut[(size_t)be * NH + lane]       = h0;
    hOut[(size_t)(be + 1) * NH + lane] = h1;
    cOut[(size_t)be * NH + lane]       = c0;
    cOut[(size_t)(be + 1) * NH + lane] = c1;
}

// ---- kernel 2: z_pred = h @ Wout^T + bout. 128-row tile per block. ----
#define TROWS 128
__global__ __launch_bounds__(256)
void proj_kernel(const float* __restrict__ Wout,
                 const float* __restrict__ bout,
                 float* __restrict__ out)
{
    __shared__ u64   sHt[TROWS][KP];     // XOR-swizzled h pairs
    __shared__ u64   sW[NL][KP];         // Wout row m pairs
    __shared__ float sB[NL];
    __shared__ float sO[TROWS * NL];

    const int tid = threadIdx.x;
    const size_t base = (size_t)blockIdx.x * TROWS;

    // NL*KP = 288 entries: strided loop over 256 threads
    for (int idx = tid; idx < NL * KP; idx += 256) {
        int m = idx / KP, k = idx % KP;
        sW[m][k] = ((const u64*)(Wout + (size_t)m * NH))[k];
    }
    if (tid < NL) sB[tid] = bout[tid];

    // coalesced load of 128x32 h tile (2048 u64), XOR-swizzled store
    const u64* hsrc = (const u64*)(g_hscr + base * NH);
    #pragma unroll
    for (int s = 0; s < 8; s++) {
        int i = tid + s * 256;
        int r = i >> 4, k = i & 15;
        sHt[r][k ^ (r & 15)] = hsrc[i];
    }
    __syncthreads();

    // 2 threads per row, 9 outputs each
    const int r = tid >> 1;
    const int q = tid & 1;
    u64 hp[KP];
    #pragma unroll
    for (int k = 0; k < KP; k++) hp[k] = sHt[r][k ^ (r & 15)];

    #pragma unroll
    for (int j = 0; j < 9; j++) {
        int m = q * 9 + j;
        u64 acc = pk(sB[m], 0.f);
        #pragma unroll
        for (int k = 0; k < KP; k++) acc = ffma2(hp[k], sW[m][k], acc);
        float lo, hi; upk(acc, lo, hi);
        sO[r * NL + m] = lo + hi;
    }
    __syncthreads();

    float* dst = out + base * NL;
    #pragma unroll
    for (int s = 0; s < (TROWS * NL) / 256; s++)   // 2304/256 = 9
        dst[tid + s * 256] = sO[tid + s * 256];
}

extern "C" void kernel_launch(void* const* d_in, const int* in_sizes, int n_in,
                              void* d_out, int out_size)
{
    const float* z    = (const float*)d_in[0];
    const float* Wih  = (const float*)d_in[1];
    const float* Whh  = (const float*)d_in[2];
    const float* bih  = (const float*)d_in[3];
    const float* bhh  = (const float*)d_in[4];
    const float* Wout = (const float*)d_in[5];
    const float* bout = (const float*)d_in[6];
    float* out = (float*)d_out;

    lstm_rec_kernel<<<NB / 16, 256>>>(z, Wih, Whh, bih, bhh, out);
    proj_kernel<<<(NB * NT) / TROWS, 256>>>(Wout, bout, out);
}

// round 10
// speedup vs baseline: 1.3800x; 1.3800x over previous
#include <cuda_runtime.h>
#include <cuda_fp16.h>

// LSTM B=2048, T=512, LATENT=18, HID=32, gates (i,f,g,o), 4H=128.
// R10 = resubmit of R9 (infra flake): tensor-core recurrence with the
// B-fragment packing fix (h2u32 bit-casts the full __half2; R8's
// __half2_raw(...).x kept only the low half -> rel_err 0.4).
// Per step: gates[16x128] = A[16x192] @ B[192x128] via mma.sync.m16n8k16
// (fp16 in, fp32 accum), K = [h16|hr|z16|zr|h16|z16] against
// B = [W16hh|W16hh|W16ih|W16ih|Wres_hh|Wres_ih] (residual-split precision).
// Block = 16 batch rows, 256 threads, 8 warps x 2 n-tiles.

#define NB 2048
#define NT 512
#define NL 18
#define NH 32
#define KS 12          // k-steps of 16 (K=192)
#define ASTR 200       // half stride of A rows
#define CSTR 136       // float stride of C rows

typedef unsigned int u32;
typedef unsigned long long u64;

__device__ float g_hscr[(size_t)NB * NT * NH];   // scratch h[B][T][32] fp32

__device__ __forceinline__ u64 pk(float x, float y) {
    u64 r; asm("mov.b64 %0,{%1,%2};" : "=l"(r) : "f"(x), "f"(y)); return r;
}
__device__ __forceinline__ void upk(u64 v, float& x, float& y) {
    asm("mov.b64 {%0,%1},%2;" : "=f"(x), "=f"(y) : "l"(v));
}
__device__ __forceinline__ u64 ffma2(u64 a, u64 b, u64 c) {
    u64 d; asm("fma.rn.f32x2 %0,%1,%2,%3;" : "=l"(d) : "l"(a), "l"(b), "l"(c));
    return d;
}
__device__ __forceinline__ float ex2(float x) {
    float r; asm("ex2.approx.f32 %0,%1;" : "=f"(r) : "f"(x)); return r;
}
__device__ __forceinline__ float rcpa(float x) {
    float r; asm("rcp.approx.f32 %0,%1;" : "=f"(r) : "f"(x)); return r;
}
__device__ __forceinline__ float sigmoid_fast(float x) {
    return rcpa(1.0f + ex2(-1.4426950408889634f * x));
}
__device__ __forceinline__ float tanh_fast(float x) {
    return 1.0f - 2.0f * rcpa(ex2(2.8853900817779268f * x) + 1.0f);
}

__device__ __forceinline__ u32 h2u32(__half a, __half b) {
    __half2 hv = __halves2half2(a, b);
    return *reinterpret_cast<u32*>(&hv);      // full 32-bit pair (R8 bug fix)
}

__device__ __forceinline__ void mma16816(float d[4], const u32 a[4], const u32 b[2]) {
    asm volatile(
        "mma.sync.aligned.m16n8k16.row.col.f32.f16.f16.f32 "
        "{%0,%1,%2,%3}, {%4,%5,%6,%7}, {%8,%9}, {%0,%1,%2,%3};"
        : "+f"(d[0]), "+f"(d[1]), "+f"(d[2]), "+f"(d[3])
        : "r"(a[0]), "r"(a[1]), "r"(a[2]), "r"(a[3]), "r"(b[0]), "r"(b[1]));
}

// B_eff[kk][n] as fp16 (main part for kk<128, residual part for kk>=128)
__device__ __forceinline__ __half w16eff(const float* Whh, const float* Wih,
                                         int n, int kk) {
    float w;
    bool res = false;
    if (kk < 32)        w = Whh[n * NH + kk];
    else if (kk < 64)   w = Whh[n * NH + (kk - 32)];
    else if (kk < 96)   { int c = kk - 64; w = (c < NL) ? Wih[n * NL + c] : 0.f; }
    else if (kk < 128)  { int c = kk - 96; w = (c < NL) ? Wih[n * NL + c] : 0.f; }
    else if (kk < 160)  { w = Whh[n * NH + (kk - 128)]; res = true; }
    else                { int c = kk - 160; w = (c < NL) ? Wih[n * NL + c] : 0.f; res = true; }
    __half h = __float2half_rn(w);
    if (!res) return h;
    return __float2half_rn(w - __half2float(h));
}

__global__ __launch_bounds__(256, 1)
void lstm_rec_tc(const float* __restrict__ z,
                 const float* __restrict__ Wih,
                 const float* __restrict__ Whh,
                 const float* __restrict__ bih,
                 const float* __restrict__ bhh,
                 float* __restrict__ out)
{
    __shared__ __half As[16][ASTR];   // kk: 0-31 h16, 32-63 hr, 64-95 z16,
                                      //     96-127 zr, 128-159 h16, 160-191 z16
    __shared__ float  Cs[16][CSTR];   // gate pre-acts (i|f|g|o blocks of 32)

    const int tid  = threadIdx.x;
    const int warp = tid >> 5;
    const int lane = tid & 31;
    const int gr   = lane >> 2;      // fragment group row 0..7
    const int tc   = lane & 3;       // thread-in-group
    const int be   = blockIdx.x * 16;

    // ---- preload B fragments (2 n-tiles per warp, 12 k-steps) ----
    u32 Bf[2][KS][2];
    #pragma unroll
    for (int jj = 0; jj < 2; jj++) {
        int n = 8 * (2 * warp + jj) + gr;   // gate column
        #pragma unroll
        for (int s = 0; s < KS; s++) {
            int k0 = 16 * s + 2 * tc;
            Bf[jj][s][0] = h2u32(w16eff(Whh, Wih, n, k0),
                                 w16eff(Whh, Wih, n, k0 + 1));
            Bf[jj][s][1] = h2u32(w16eff(Whh, Wih, n, k0 + 8),
                                 w16eff(Whh, Wih, n, k0 + 9));
        }
    }
    // bias for my D cols (tile jj cols 8j+2tc, +1), same for rows gr, gr+8
    float bj[2][2];
    #pragma unroll
    for (int jj = 0; jj < 2; jj++) {
        int n = 8 * (2 * warp + jj) + 2 * tc;
        bj[jj][0] = bih[n]     + bhh[n];
        bj[jj][1] = bih[n + 1] + bhh[n + 1];
    }

    // ---- zero A buffer ----
    for (int i = tid; i < 16 * (ASTR / 2); i += 256)
        ((u32*)As)[i] = 0u;
    __syncthreads();

    // pointwise mapping: thread -> (row pr, hidden units l0, l0+1)
    const int pr = tid >> 4;
    const int pq = tid & 15;
    const int l0 = 2 * pq;
    float cst0 = 0.f, cst1 = 0.f, hv0 = 0.f, hv1 = 0.f;

    // z(0) into A, prefetch z(1)
    float2 zn = make_float2(0.f, 0.f);
    if (pq < 9) {
        float2 z0v = *(const float2*)(z + ((size_t)(be + pr) * NT + 0) * NL + l0);
        __half2 z16 = __floats2half2_rn(z0v.x, z0v.y);
        float2 zb = __half22float2(z16);
        __half2 zr = __floats2half2_rn(z0v.x - zb.x, z0v.y - zb.y);
        *(__half2*)&As[pr][64 + l0]  = z16;
        *(__half2*)&As[pr][160 + l0] = z16;
        *(__half2*)&As[pr][96 + l0]  = zr;
        zn = *(const float2*)(z + ((size_t)(be + pr) * NT + 1) * NL + l0);
    }
    __syncthreads();

    for (int t = 0; t < NT; t++) {
        // ---- phase 1: mma (8 warps x 2 n-tiles) ----
        float d0[4] = {bj[0][0], bj[0][1], bj[0][0], bj[0][1]};
        float d1[4] = {bj[1][0], bj[1][1], bj[1][0], bj[1][1]};
        #pragma unroll
        for (int s = 0; s < KS; s++) {
            u32 a[4];
            int k0 = 16 * s + 2 * tc;
            a[0] = *(const u32*)&As[gr][k0];
            a[1] = *(const u32*)&As[gr + 8][k0];
            a[2] = *(const u32*)&As[gr][k0 + 8];
            a[3] = *(const u32*)&As[gr + 8][k0 + 8];
            mma16816(d0, a, Bf[0][s]);
            mma16816(d1, a, Bf[1][s]);
        }
        {
            int t0 = 8 * (2 * warp) + 2 * tc;
            int t1 = 8 * (2 * warp + 1) + 2 * tc;
            *(float2*)&Cs[gr][t0]     = make_float2(d0[0], d0[1]);
            *(float2*)&Cs[gr + 8][t0] = make_float2(d0[2], d0[3]);
            *(float2*)&Cs[gr][t1]     = make_float2(d1[0], d1[1]);
            *(float2*)&Cs[gr + 8][t1] = make_float2(d1[2], d1[3]);
        }
        __syncthreads();

        // ---- phase 2: pointwise (2 hidden units per thread) ----
        float2 gi = *(const float2*)&Cs[pr][0  + l0];
        float2 gf = *(const float2*)&Cs[pr][32 + l0];
        float2 gg = *(const float2*)&Cs[pr][64 + l0];
        float2 go = *(const float2*)&Cs[pr][96 + l0];

        {
            float ii = sigmoid_fast(gi.x), ff = sigmoid_fast(gf.x);
            float g  = tanh_fast(gg.x),    oo = sigmoid_fast(go.x);
            cst0 = ff * cst0 + ii * g;
            hv0 = oo * tanh_fast(cst0);
        }
        {
            float ii = sigmoid_fast(gi.y), ff = sigmoid_fast(gf.y);
            float g  = tanh_fast(gg.y),    oo = sigmoid_fast(go.y);
            cst1 = ff * cst1 + ii * g;
            hv1 = oo * tanh_fast(cst1);
        }

        // pack h -> fp16 + residual into A (operands for step t+1)
        __half2 h16 = __floats2half2_rn(hv0, hv1);
        float2 hb = __half22float2(h16);
        __half2 hr = __floats2half2_rn(hv0 - hb.x, hv1 - hb.y);
        *(__half2*)&As[pr][0   + l0] = h16;
        *(__half2*)&As[pr][128 + l0] = h16;
        *(__half2*)&As[pr][32  + l0] = hr;

        // z for step t+1 (from prefetched zn), prefetch z(t+2)
        if (pq < 9) {
            __half2 z16 = __floats2half2_rn(zn.x, zn.y);
            float2 zb = __half22float2(z16);
            __half2 zr = __floats2half2_rn(zn.x - zb.x, zn.y - zb.y);
            *(__half2*)&As[pr][64 + l0]  = z16;
            *(__half2*)&As[pr][160 + l0] = z16;
            *(__half2*)&As[pr][96 + l0]  = zr;
            if (t + 2 < NT)
                zn = *(const float2*)(z + ((size_t)(be + pr) * NT + t + 2) * NL + l0);
        }

        // h (fp32) to scratch for projection
        *(float2*)&g_hscr[((size_t)(be + pr) * NT + t) * NH + l0] =
            make_float2(hv0, hv1);

        __syncthreads();
    }

    // out layout: [z_pred (B*T*18) | h_n (B*32) | c_n (B*32)]
    float* hOut = out + (size_t)NB * NT * NL;
    float* cOut = hOut + (size_t)NB * NH;
    *(float2*)&hOut[(size_t)(be + pr) * NH + l0] = make_float2(hv0, hv1);
    *(float2*)&cOut[(size_t)(be + pr) * NH + l0] = make_float2(cst0, cst1);
}

// ---- kernel 2: z_pred = h @ Wout^T + bout. 128-row tile per block. ----
#define KP 16
#define TROWS 128
__global__ __launch_bounds__(256)
void proj_kernel(const float* __restrict__ Wout,
                 const float* __restrict__ bout,
                 float* __restrict__ out)
{
    __shared__ u64   sHt[TROWS][KP];     // XOR-swizzled h pairs
    __shared__ u64   sW[NL][KP];         // Wout row m pairs
    __shared__ float sB[NL];
    __shared__ float sO[TROWS * NL];

    const int tid = threadIdx.x;
    const size_t base = (size_t)blockIdx.x * TROWS;

    for (int idx = tid; idx < NL * KP; idx += 256) {
        int m = idx / KP, k = idx % KP;
        sW[m][k] = ((const u64*)(Wout + (size_t)m * NH))[k];
    }
    if (tid < NL) sB[tid] = bout[tid];

    const u64* hsrc = (const u64*)(g_hscr + base * NH);
    #pragma unroll
    for (int s = 0; s < 8; s++) {
        int i = tid + s * 256;
        int r = i >> 4, k = i & 15;
        sHt[r][k ^ (r & 15)] = hsrc[i];
    }
    __syncthreads();

    const int r = tid >> 1;
    const int q = tid & 1;
    u64 hp[KP];
    #pragma unroll
    for (int k = 0; k < KP; k++) hp[k] = sHt[r][k ^ (r & 15)];

    #pragma unroll
    for (int j = 0; j < 9; j++) {
        int m = q * 9 + j;
        u64 acc = pk(sB[m], 0.f);
        #pragma unroll
        for (int k = 0; k < KP; k++) acc = ffma2(hp[k], sW[m][k], acc);
        float lo, hi; upk(acc, lo, hi);
        sO[r * NL + m] = lo + hi;
    }
    __syncthreads();

    float* dst = out + base * NL;
    #pragma unroll
    for (int s = 0; s < (TROWS * NL) / 256; s++)
        dst[tid + s * 256] = sO[tid + s * 256];
}

extern "C" void kernel_launch(void* const* d_in, const int* in_sizes, int n_in,
                              void* d_out, int out_size)
{
    const float* z    = (const float*)d_in[0];
    const float* Wih  = (const float*)d_in[1];
    const float* Whh  = (const float*)d_in[2];
    const float* bih  = (const float*)d_in[3];
    const float* bhh  = (const float*)d_in[4];
    const float* Wout = (const float*)d_in[5];
    const float* bout = (const float*)d_in[6];
    float* out = (float*)d_out;

    lstm_rec_tc<<<NB / 16, 256>>>(z, Wih, Whh, bih, bhh, out);
    proj_kernel<<<(NB * NT) / TROWS, 256>>>(Wout, bout, out);
}

// round 11
// speedup vs baseline: 1.5483x; 1.1219x over previous
#include <cuda_runtime.h>
#include <cuda_fp16.h>

// LSTM B=2048, T=512, LATENT=18, HID=32, gates (i,f,g,o), 4H=128.
// R11: single fused kernel. Tensor-core recurrence (R10, validated at
// rel_err 3.5e-7) extended with 3 projection n8-tiles: B cols 128..145 hold
// [Wout16|Wout16|Wres_out] against A k-sections [h16|hr|...|h16|...], so the
// MMA at iteration t emits z_pred_{t-1} alongside the gates. proj_kernel and
// the 134MB h scratch are gone. Loop runs NT+1 iterations; z_pred[t-1]
// stored from Cs cols 128+ after the phase-1 barrier.
// Block = 16 batch rows, 256 threads, 8 warps x 2 gate-tiles (+1 proj tile
// on warps 0..2, only 6 live k-steps each).

#define NB 2048
#define NT 512
#define NL 18
#define NH 32
#define KS 12          // k-steps of 16 (K=192)
#define ASTR 200       // half stride of A rows
#define CSTR 152       // float stride of C rows (128 gate + 18 proj + pad)

typedef unsigned int u32;

__device__ __forceinline__ float ex2(float x) {
    float r; asm("ex2.approx.f32 %0,%1;" : "=f"(r) : "f"(x)); return r;
}
__device__ __forceinline__ float rcpa(float x) {
    float r; asm("rcp.approx.f32 %0,%1;" : "=f"(r) : "f"(x)); return r;
}
__device__ __forceinline__ float sigmoid_fast(float x) {
    return rcpa(1.0f + ex2(-1.4426950408889634f * x));
}
__device__ __forceinline__ float tanh_fast(float x) {
    return 1.0f - 2.0f * rcpa(ex2(2.8853900817779268f * x) + 1.0f);
}

__device__ __forceinline__ u32 h2u32(__half a, __half b) {
    __half2 hv = __halves2half2(a, b);
    return *reinterpret_cast<u32*>(&hv);
}

__device__ __forceinline__ void mma16816(float d[4], const u32 a[4], const u32 b[2]) {
    asm volatile(
        "mma.sync.aligned.m16n8k16.row.col.f32.f16.f16.f32 "
        "{%0,%1,%2,%3}, {%4,%5,%6,%7}, {%8,%9}, {%0,%1,%2,%3};"
        : "+f"(d[0]), "+f"(d[1]), "+f"(d[2]), "+f"(d[3])
        : "r"(a[0]), "r"(a[1]), "r"(a[2]), "r"(a[3]), "r"(b[0]), "r"(b[1]));
}

// Gate B_eff[kk][n], n = gate row 0..127 (main part kk<128, residual kk>=128)
__device__ __forceinline__ __half w16eff(const float* Whh, const float* Wih,
                                         int n, int kk) {
    float w;
    bool res = false;
    if (kk < 32)        w = Whh[n * NH + kk];
    else if (kk < 64)   w = Whh[n * NH + (kk - 32)];
    else if (kk < 96)   { int c = kk - 64; w = (c < NL) ? Wih[n * NL + c] : 0.f; }
    else if (kk < 128)  { int c = kk - 96; w = (c < NL) ? Wih[n * NL + c] : 0.f; }
    else if (kk < 160)  { w = Whh[n * NH + (kk - 128)]; res = true; }
    else                { int c = kk - 160; w = (c < NL) ? Wih[n * NL + c] : 0.f; res = true; }
    __half h = __float2half_rn(w);
    if (!res) return h;
    return __float2half_rn(w - __half2float(h));
}

// Projection B_eff[kk][m], m = latent 0..17.
// kk0-31 (A=h16): Wout16 ; kk32-63 (A=hr): Wout16 ; kk128-159 (A=h16): Wres.
__device__ __forceinline__ __half wout_eff(const float* Wout, int m, int kk) {
    if (m >= NL) return __float2half_rn(0.f);
    float w; bool res = false;
    if (kk < 32)        w = Wout[m * NH + kk];
    else if (kk < 64)   w = Wout[m * NH + (kk - 32)];
    else if (kk < 128)  return __float2half_rn(0.f);
    else if (kk < 160)  { w = Wout[m * NH + (kk - 128)]; res = true; }
    else                return __float2half_rn(0.f);
    __half h = __float2half_rn(w);
    if (!res) return h;
    return __float2half_rn(w - __half2float(h));
}

__global__ __launch_bounds__(256, 1)
void lstm_fused_tc(const float* __restrict__ z,
                   const float* __restrict__ Wih,
                   const float* __restrict__ Whh,
                   const float* __restrict__ bih,
                   const float* __restrict__ bhh,
                   const float* __restrict__ Wout,
                   const float* __restrict__ bout,
                   float* __restrict__ out)
{
    __shared__ __half As[16][ASTR];   // kk: 0-31 h16, 32-63 hr, 64-95 z16,
                                      //     96-127 zr, 128-159 h16, 160-191 z16
    __shared__ float  Cs[16][CSTR];   // cols 0-127 gates i|f|g|o, 128-145 z_pred

    const int tid  = threadIdx.x;
    const int warp = tid >> 5;
    const int lane = tid & 31;
    const int gr   = lane >> 2;
    const int tc   = lane & 3;
    const int be   = blockIdx.x * 16;

    // ---- gate B fragments (2 n-tiles per warp) ----
    u32 Bf[2][KS][2];
    #pragma unroll
    for (int jj = 0; jj < 2; jj++) {
        int n = 8 * (2 * warp + jj) + gr;
        #pragma unroll
        for (int s = 0; s < KS; s++) {
            int k0 = 16 * s + 2 * tc;
            Bf[jj][s][0] = h2u32(w16eff(Whh, Wih, n, k0),
                                 w16eff(Whh, Wih, n, k0 + 1));
            Bf[jj][s][1] = h2u32(w16eff(Whh, Wih, n, k0 + 8),
                                 w16eff(Whh, Wih, n, k0 + 9));
        }
    }
    float bj[2][2];
    #pragma unroll
    for (int jj = 0; jj < 2; jj++) {
        int n = 8 * (2 * warp + jj) + 2 * tc;
        bj[jj][0] = bih[n]     + bhh[n];
        bj[jj][1] = bih[n + 1] + bhh[n + 1];
    }

    // ---- projection tile (warps 0..2) ----
    u32 Bp[KS][2];
    float bp0 = 0.f, bp1 = 0.f;
    if (warp < 3) {
        int m = 8 * warp + gr;
        #pragma unroll
        for (int s = 0; s < KS; s++) {
            int k0 = 16 * s + 2 * tc;
            Bp[s][0] = h2u32(wout_eff(Wout, m, k0),     wout_eff(Wout, m, k0 + 1));
            Bp[s][1] = h2u32(wout_eff(Wout, m, k0 + 8), wout_eff(Wout, m, k0 + 9));
        }
        int mc = 8 * warp + 2 * tc;
        bp0 = (mc     < NL) ? bout[mc]     : 0.f;
        bp1 = (mc + 1 < NL) ? bout[mc + 1] : 0.f;
    }

    // ---- zero A buffer (h=0 initial state; z sections filled below) ----
    for (int i = tid; i < 16 * (ASTR / 2); i += 256)
        ((u32*)As)[i] = 0u;
    __syncthreads();

    // pointwise mapping: thread -> (row pr, hidden units l0, l0+1)
    const int pr = tid >> 4;
    const int pq = tid & 15;
    const int l0 = 2 * pq;
    float cst0 = 0.f, cst1 = 0.f, hv0 = 0.f, hv1 = 0.f;

    // z(0) into A, prefetch z(1)
    float2 zn = make_float2(0.f, 0.f);
    if (pq < 9) {
        float2 z0v = *(const float2*)(z + ((size_t)(be + pr) * NT + 0) * NL + l0);
        __half2 z16 = __floats2half2_rn(z0v.x, z0v.y);
        float2 zb = __half22float2(z16);
        __half2 zr = __floats2half2_rn(z0v.x - zb.x, z0v.y - zb.y);
        *(__half2*)&As[pr][64 + l0]  = z16;
        *(__half2*)&As[pr][160 + l0] = z16;
        *(__half2*)&As[pr][96 + l0]  = zr;
        zn = *(const float2*)(z + ((size_t)(be + pr) * NT + 1) * NL + l0);
    }
    __syncthreads();

    for (int t = 0; t <= NT; t++) {
        // ---- phase 1: MMA (gates + projection of h from step t-1) ----
        float d0[4] = {bj[0][0], bj[0][1], bj[0][0], bj[0][1]};
        float d1[4] = {bj[1][0], bj[1][1], bj[1][0], bj[1][1]};
        float dp[4] = {bp0, bp1, bp0, bp1};
        #pragma unroll
        for (int s = 0; s < KS; s++) {
            u32 a[4];
            int k0 = 16 * s + 2 * tc;
            a[0] = *(const u32*)&As[gr][k0];
            a[1] = *(const u32*)&As[gr + 8][k0];
            a[2] = *(const u32*)&As[gr][k0 + 8];
            a[3] = *(const u32*)&As[gr + 8][k0 + 8];
            mma16816(d0, a, Bf[0][s]);
            mma16816(d1, a, Bf[1][s]);
            if (warp < 3 && (s < 4 || s == 8 || s == 9))   // live proj k-steps
                mma16816(dp, a, Bp[s]);
        }
        {
            int t0 = 8 * (2 * warp) + 2 * tc;
            int t1 = 8 * (2 * warp + 1) + 2 * tc;
            *(float2*)&Cs[gr][t0]     = make_float2(d0[0], d0[1]);
            *(float2*)&Cs[gr + 8][t0] = make_float2(d0[2], d0[3]);
            *(float2*)&Cs[gr][t1]     = make_float2(d1[0], d1[1]);
            *(float2*)&Cs[gr + 8][t1] = make_float2(d1[2], d1[3]);
            if (warp < 3) {
                int tp = 128 + 8 * warp + 2 * tc;
                *(float2*)&Cs[gr][tp]     = make_float2(dp[0], dp[1]);
                *(float2*)&Cs[gr + 8][tp] = make_float2(dp[2], dp[3]);
            }
        }
        __syncthreads();

        // ---- z_pred[t-1] store (h of step t-1 was in A during this MMA) ----
        if (t >= 1 && pq < 9) {
            float2 zp = *(const float2*)&Cs[pr][128 + l0];
            *(float2*)(out + ((size_t)(be + pr) * NT + (t - 1)) * NL + l0) = zp;
        }

        // ---- phase 2: pointwise + A update (skip on the extra iteration) ----
        if (t < NT) {
            float2 gi = *(const float2*)&Cs[pr][0  + l0];
            float2 gf = *(const float2*)&Cs[pr][32 + l0];
            float2 gg = *(const float2*)&Cs[pr][64 + l0];
            float2 go = *(const float2*)&Cs[pr][96 + l0];

            {
                float ii = sigmoid_fast(gi.x), ff = sigmoid_fast(gf.x);
                float g  = tanh_fast(gg.x),    oo = sigmoid_fast(go.x);
                cst0 = ff * cst0 + ii * g;
                hv0 = oo * tanh_fast(cst0);
            }
            {
                float ii = sigmoid_fast(gi.y), ff = sigmoid_fast(gf.y);
                float g  = tanh_fast(gg.y),    oo = sigmoid_fast(go.y);
                cst1 = ff * cst1 + ii * g;
                hv1 = oo * tanh_fast(cst1);
            }

            __half2 h16 = __floats2half2_rn(hv0, hv1);
            float2 hb = __half22float2(h16);
            __half2 hr = __floats2half2_rn(hv0 - hb.x, hv1 - hb.y);
            *(__half2*)&As[pr][0   + l0] = h16;
            *(__half2*)&As[pr][128 + l0] = h16;
            *(__half2*)&As[pr][32  + l0] = hr;

            if (pq < 9) {
                __half2 z16 = __floats2half2_rn(zn.x, zn.y);
                float2 zb = __half22float2(z16);
                __half2 zr = __floats2half2_rn(zn.x - zb.x, zn.y - zb.y);
                *(__half2*)&As[pr][64 + l0]  = z16;
                *(__half2*)&As[pr][160 + l0] = z16;
                *(__half2*)&As[pr][96 + l0]  = zr;
                if (t + 2 < NT)
                    zn = *(const float2*)(z + ((size_t)(be + pr) * NT + t + 2) * NL + l0);
            }
        }
        __syncthreads();
    }

    // out layout: [z_pred (B*T*18) | h_n (B*32) | c_n (B*32)]
    float* hOut = out + (size_t)NB * NT * NL;
    float* cOut = hOut + (size_t)NB * NH;
    *(float2*)&hOut[(size_t)(be + pr) * NH + l0] = make_float2(hv0, hv1);
    *(float2*)&cOut[(size_t)(be + pr) * NH + l0] = make_float2(cst0, cst1);
}

extern "C" void kernel_launch(void* const* d_in, const int* in_sizes, int n_in,
                              void* d_out, int out_size)
{
    const float* z    = (const float*)d_in[0];
    const float* Wih  = (const float*)d_in[1];
    const float* Whh  = (const float*)d_in[2];
    const float* bih  = (const float*)d_in[3];
    const float* bhh  = (const float*)d_in[4];
    const float* Wout = (const float*)d_in[5];
    const float* bout = (const float*)d_in[6];
    float* out = (float*)d_out;

    lstm_fused_tc<<<NB / 16, 256>>>(z, Wih, Whh, bih, bhh, Wout, bout, out);
}